// round 11
// baseline (speedup 1.0000x reference)
#include <cuda_runtime.h>

// Conv2D valid cross-correlation: x[4096,4096] fp32 * w[15,15] + bias -> out[4082,4082]
//
// v10: v5 (cmem scalar weights, RY=4, SSTR=144) with the steady loop FULLY
//  unrolled so every weight access c_w2[literal] has an immediate const
//  address -> ptxas emits LDCU (UR dest, floor 1) and FFMA2 takes the weight
//  from a UNIFORM register. That cuts FFMA2's GPR reads from 3-even/3-odd
//  (rt 3 by RF banking -> the measured rt ~2.8 plateau, invariant v4 vs v5)
//  to 2/2 (rt 2). v5's runtime weight pointer forced LDC->GPR (floor 8).
//  __launch_bounds__(256,4): regs <= 64 (v5 natural 58; no squeeze, no spill).

#define Hd 4096
#define Wd 4096
#define KHd 15
#define KWd 15
#define OHd (Hd - KHd + 1)   // 4082
#define OWd (Wd - KWd + 1)   // 4082

#define BXo 128
#define BYo 64
#define RY 4
#define TILE_ROWS (BYo + KHd - 1)   // 78
#define SSTR 144                     // floats per smem row

typedef unsigned long long u64;

__constant__ u64 c_w2[KHd * KWd];    // (w,w) duplicated pairs, row-major 15x15

__device__ __forceinline__ u64 pack2(float lo, float hi) {
    u64 r;
    asm("mov.b64 %0, {%1, %2};" : "=l"(r) : "f"(lo), "f"(hi));
    return r;
}

__device__ __forceinline__ u64 fma2(u64 a, u64 b, u64 c) {
    u64 d;
    asm("fma.rn.f32x2 %0, %1, %2, %3;" : "=l"(d) : "l"(a), "l"(b), "l"(c));
    return d;
}

// odd pair = {hi(a), lo(b)} : exactly 2 SASS MOVs
__device__ __forceinline__ u64 mkodd(u64 a, u64 b) {
    u64 r;
    asm("{\n\t"
        ".reg .b32 al, ah, bl, bh;\n\t"
        "mov.b64 {al, ah}, %1;\n\t"
        "mov.b64 {bl, bh}, %2;\n\t"
        "mov.b64 %0, {ah, bl};\n\t"
        "}" : "=l"(r) : "l"(a), "l"(b));
    return r;
}

// One ky-row of the stencil applied to 4 output pairs of one output row.
// wbase MUST be a compile-time constant at every call site (full unroll) so
// c_w2[wbase+kx] is an immediate const address -> LDCU -> UR operand.
__device__ __forceinline__ void conv_row(u64 acc[4], int wbase,
                                         const u64 ev[12], const u64 od[10]) {
#pragma unroll
    for (int kx = 0; kx < KWd; ++kx) {
        u64 w2 = c_w2[wbase + kx];
        if ((kx & 1) == 0) {
#pragma unroll
            for (int p = 0; p < 4; ++p)
                acc[p] = fma2(ev[(kx >> 1) + p], w2, acc[p]);
        } else {
#pragma unroll
            for (int p = 0; p < 4; ++p)
                acc[p] = fma2(od[(kx >> 1) + p], w2, acc[p]);
        }
    }
}

// Load 12 even pairs (direct ulonglong2) and derive 10 odd pairs (2 MOVs each).
__device__ __forceinline__ void load_row(const float* __restrict__ srow,
                                         u64 ev[12], u64 od[10]) {
#pragma unroll
    for (int i = 0; i < 6; ++i) {
        ulonglong2 v = ((const ulonglong2*)srow)[i];
        ev[2 * i + 0] = v.x;
        ev[2 * i + 1] = v.y;
    }
#pragma unroll
    for (int j = 0; j < 10; ++j)
        od[j] = mkodd(ev[j], ev[j + 1]);
}

__global__ __launch_bounds__(256, 4)
void conv2d_f32x2_kernel(const float* __restrict__ x,
                         const float* __restrict__ bias,
                         float* __restrict__ out) {
    __shared__ float s_in[TILE_ROWS * SSTR];   // 78*144*4 = 44928 B

    const int tid = threadIdx.x;
    const int tx0 = blockIdx.x * BXo;
    const int ty0 = blockIdx.y * BYo;

    // Stage input tile: 78 rows x 144 floats.
    for (int s = tid; s < TILE_ROWS * 36; s += 256) {
        int rr = s / 36;
        int cc = (s - rr * 36) * 4;
        int gy = ty0 + rr;
        int gx = tx0 + cc;
        float4 v;
        if (gy < Hd && gx + 3 < Wd) {
            v = *(const float4*)(x + (size_t)gy * Wd + gx);
        } else {
            v.x = (gy < Hd && gx + 0 < Wd) ? x[(size_t)gy * Wd + gx + 0] : 0.f;
            v.y = (gy < Hd && gx + 1 < Wd) ? x[(size_t)gy * Wd + gx + 1] : 0.f;
            v.z = (gy < Hd && gx + 2 < Wd) ? x[(size_t)gy * Wd + gx + 2] : 0.f;
            v.w = (gy < Hd && gx + 3 < Wd) ? x[(size_t)gy * Wd + gx + 3] : 0.f;
        }
        *(float4*)&s_in[rr * SSTR + cc] = v;
    }
    __syncthreads();

    const int tx = tid & 15;
    const int ty = tid >> 4;
    const int oxl = tx * 8;        // 8 outputs in x
    const int oyl = ty * RY;       // 4 outputs in y

    const float b = bias[0];
    const u64 b2 = pack2(b, b);
    u64 acc[RY][4];
#pragma unroll
    for (int j = 0; j < RY; ++j)
#pragma unroll
        for (int p = 0; p < 4; ++p) acc[j][p] = b2;

    u64 ev[12], od[10];
    const float* sbase = &s_in[oyl * SSTR + oxl];

    // Prologue: r = 0,1,2 (all weight indices literal)
    load_row(sbase + 0 * SSTR, ev, od);
    conv_row(acc[0], 0 * KWd, ev, od);

    load_row(sbase + 1 * SSTR, ev, od);
    conv_row(acc[0], 1 * KWd, ev, od);
    conv_row(acc[1], 0 * KWd, ev, od);

    load_row(sbase + 2 * SSTR, ev, od);
    conv_row(acc[0], 2 * KWd, ev, od);
    conv_row(acc[1], 1 * KWd, ev, od);
    conv_row(acc[2], 0 * KWd, ev, od);

    // Steady: r = 3..14, FULLY unrolled -> every weight index is a literal
    // immediate const address (LDCU / UR path).
#pragma unroll
    for (int r = 3; r < KHd; ++r) {
        load_row(sbase + r * SSTR, ev, od);
        conv_row(acc[0], (r    ) * KWd, ev, od);
        conv_row(acc[1], (r - 1) * KWd, ev, od);
        conv_row(acc[2], (r - 2) * KWd, ev, od);
        conv_row(acc[3], (r - 3) * KWd, ev, od);
    }

    // Epilogue: r = 15,16,17
    load_row(sbase + 15 * SSTR, ev, od);
    conv_row(acc[1], 14 * KWd, ev, od);
    conv_row(acc[2], 13 * KWd, ev, od);
    conv_row(acc[3], 12 * KWd, ev, od);

    load_row(sbase + 16 * SSTR, ev, od);
    conv_row(acc[2], 14 * KWd, ev, od);
    conv_row(acc[3], 13 * KWd, ev, od);

    load_row(sbase + 17 * SSTR, ev, od);
    conv_row(acc[3], 14 * KWd, ev, od);

    // Store: even-aligned 8B pairs; OW=4082 even -> pairs never straddle rows.
    const int oxg = tx0 + oxl;
#pragma unroll
    for (int j = 0; j < RY; ++j) {
        int oy = ty0 + oyl + j;
        if (oy < OHd) {
            float* orow = out + (size_t)oy * OWd;
#pragma unroll
            for (int p = 0; p < 4; ++p) {
                int ox = oxg + 2 * p;
                if (ox < OWd) {
                    *(u64*)(orow + ox) = acc[j][p];
                }
            }
        }
    }
}

extern "C" void kernel_launch(void* const* d_in, const int* in_sizes, int n_in,
                              void* d_out, int out_size) {
    const float* x    = (const float*)d_in[0];
    const float* wt   = (const float*)d_in[1];
    const float* bias = (const float*)d_in[2];
    float* out        = (float*)d_out;

    // Build (w,w) u64 pairs in __constant__ memory (async D2D, graph-capturable).
    void* cw_addr = nullptr;
    cudaGetSymbolAddress(&cw_addr, c_w2);
    cudaMemcpy2DAsync(cw_addr, 8, wt, 4, 4, KHd * KWd,
                      cudaMemcpyDeviceToDevice, 0);
    cudaMemcpy2DAsync((char*)cw_addr + 4, 8, wt, 4, 4, KHd * KWd,
                      cudaMemcpyDeviceToDevice, 0);

    dim3 grid((OWd + BXo - 1) / BXo, (OHd + BYo - 1) / BYo);  // (32, 64)
    conv2d_f32x2_kernel<<<grid, 256>>>(x, bias, out);
}

// round 14
// speedup vs baseline: 1.8255x; 1.8255x over previous
#include <cuda_runtime.h>

// Conv2D valid cross-correlation: x[4096,4096] fp32 * w[15,15] + bias -> out[4082,4082]
//
// v11: v4 base (RY=2, cmem weights, regs 38, 137us) + LDC.128 weight pair
//  loads through EXPLICIT const-space asm (cvta.to.const + ld.const.v2.u64).
//  Theory: v4's 60 scalar LDC per row-step hit the GPR-dest const-port floor
//  (8 cyc/SMSP) = 480 cyc, co-saturating with 240 FFMA2 * rt2 = 480 fma cyc.
//  Pair loads cut that to 16 loads = 128 cyc -> fma pipe sole limiter.
//  v8 tried this with a C pointer cast and ptxas dropped the const space
//  (generic loads, L2 3x); asm cannot be mis-inferred.
//  Row parity (15r odd/even vs 16B alignment) via conv_row<P>, loop unrolled x2.

#define Hd 4096
#define Wd 4096
#define KHd 15
#define KWd 15
#define OHd (Hd - KHd + 1)   // 4082
#define OWd (Wd - KWd + 1)   // 4082

#define BXo 128
#define BYo 32
#define TILE_ROWS (BYo + KHd - 1)   // 46
#define SSTR 144                     // floats per smem row

typedef unsigned long long u64;

// (w,w) pairs, rows contiguous (15 u64/row), padded so the aligned 16-u64
// window of row 14 (indices 210..225) stays in bounds.
__constant__ __align__(16) u64 c_w2[240];

__device__ __forceinline__ u64 pack2(float lo, float hi) {
    u64 r;
    asm("mov.b64 %0, {%1, %2};" : "=l"(r) : "f"(lo), "f"(hi));
    return r;
}

__device__ __forceinline__ u64 fma2(u64 a, u64 b, u64 c) {
    u64 d;
    asm("fma.rn.f32x2 %0, %1, %2, %3;" : "=l"(d) : "l"(a), "l"(b), "l"(c));
    return d;
}

// odd pair = {hi(a), lo(b)} : exactly 2 SASS MOVs
__device__ __forceinline__ u64 mkodd(u64 a, u64 b) {
    u64 r;
    asm("{\n\t"
        ".reg .b32 al, ah, bl, bh;\n\t"
        "mov.b64 {al, ah}, %1;\n\t"
        "mov.b64 {bl, bh}, %2;\n\t"
        "mov.b64 %0, {ah, bl};\n\t"
        "}" : "=l"(r) : "l"(a), "l"(b));
    return r;
}

// One ky-row of the stencil on 4 output pairs. Weight row `row` (parity P ==
// row & 1) read as 8x LDC.128 from the 16B-aligned window starting at
// element 15*row - P:
//   P=0: q[i] = (w[2i], w[2i+1])   (q[7].y unused)
//   P=1: q[i] = (w[2i-1], w[2i])   (q[0].x unused)
template<int P>
__device__ __forceinline__ void conv_row(u64 acc[4], u64 cb, int row,
                                         const u64 ev[12], const u64 od[10]) {
    u64 base = cb + (u64)(15 * row - P) * 8u;
#pragma unroll
    for (int i = 0; i < 8; ++i) {
        u64 wx, wy;
        asm("ld.const.v2.u64 {%0, %1}, [%2];"
            : "=l"(wx), "=l"(wy) : "l"(base + 16u * i));
        if (P == 0) {
#pragma unroll
            for (int p = 0; p < 4; ++p)
                acc[p] = fma2(ev[i + p], wx, acc[p]);
            if (i < 7) {
#pragma unroll
                for (int p = 0; p < 4; ++p)
                    acc[p] = fma2(od[i + p], wy, acc[p]);
            }
        } else {
#pragma unroll
            for (int p = 0; p < 4; ++p)
                acc[p] = fma2(ev[i + p], wy, acc[p]);
            if (i >= 1) {
#pragma unroll
                for (int p = 0; p < 4; ++p)
                    acc[p] = fma2(od[i - 1 + p], wx, acc[p]);
            }
        }
    }
}

// Load 12 even pairs (direct ulonglong2) and derive 10 odd pairs (2 MOVs each).
__device__ __forceinline__ void load_row(const float* __restrict__ srow,
                                         u64 ev[12], u64 od[10]) {
#pragma unroll
    for (int i = 0; i < 6; ++i) {
        ulonglong2 v = ((const ulonglong2*)srow)[i];
        ev[2 * i + 0] = v.x;
        ev[2 * i + 1] = v.y;
    }
#pragma unroll
    for (int j = 0; j < 10; ++j)
        od[j] = mkodd(ev[j], ev[j + 1]);
}

__global__ __launch_bounds__(256, 3)
void conv2d_f32x2_kernel(const float* __restrict__ x,
                         const float* __restrict__ bias,
                         float* __restrict__ out) {
    __shared__ float s_in[TILE_ROWS * SSTR];   // 46*144*4 = 26496 B

    const int tid = threadIdx.x;
    const int tx0 = blockIdx.x * BXo;
    const int ty0 = blockIdx.y * BYo;

    // Stage input tile: 46 rows x 144 floats.
    for (int s = tid; s < TILE_ROWS * 36; s += 256) {
        int rr = s / 36;
        int cc = (s - rr * 36) * 4;
        int gy = ty0 + rr;
        int gx = tx0 + cc;
        float4 v;
        if (gy < Hd && gx + 3 < Wd) {
            v = *(const float4*)(x + (size_t)gy * Wd + gx);
        } else {
            v.x = (gy < Hd && gx + 0 < Wd) ? x[(size_t)gy * Wd + gx + 0] : 0.f;
            v.y = (gy < Hd && gx + 1 < Wd) ? x[(size_t)gy * Wd + gx + 1] : 0.f;
            v.z = (gy < Hd && gx + 2 < Wd) ? x[(size_t)gy * Wd + gx + 2] : 0.f;
            v.w = (gy < Hd && gx + 3 < Wd) ? x[(size_t)gy * Wd + gx + 3] : 0.f;
        }
        *(float4*)&s_in[rr * SSTR + cc] = v;
    }
    __syncthreads();

    // Const-space base address of c_w2 (explicit: cannot lose the space).
    u64 cb;
    asm("cvta.to.const.u64 %0, %1;" : "=l"(cb) : "l"((const u64*)c_w2));

    const int tx = tid & 15;
    const int ty = tid >> 4;
    const int oxl = tx * 8;   // 8 outputs in x
    const int oyl = ty * 2;   // 2 outputs in y

    const float b = bias[0];
    const u64 b2 = pack2(b, b);
    u64 acc0[4] = {b2, b2, b2, b2};
    u64 acc1[4] = {b2, b2, b2, b2};

    u64 ev[12], od[10];
    const float* sbase = &s_in[oyl * SSTR + oxl];

    // r = 0: only output row 0 (weight row 0, parity 0)
    load_row(sbase + 0 * SSTR, ev, od);
    conv_row<0>(acc0, cb, 0, ev, od);

    // r = 1..14, x2 unrolled so weight-row parity is compile-time.
#pragma unroll 1
    for (int r = 1; r <= 13; r += 2) {
        // input row r (odd): acc0 uses weight row r (P=1), acc1 row r-1 (P=0)
        load_row(sbase + r * SSTR, ev, od);
        conv_row<1>(acc0, cb, r,     ev, od);
        conv_row<0>(acc1, cb, r - 1, ev, od);
        // input row r+1 (even): acc0 row r+1 (P=0), acc1 row r (P=1)
        load_row(sbase + (r + 1) * SSTR, ev, od);
        conv_row<0>(acc0, cb, r + 1, ev, od);
        conv_row<1>(acc1, cb, r,     ev, od);
    }

    // r = 15: only output row 1 (weight row 14, parity 0)
    load_row(sbase + 15 * SSTR, ev, od);
    conv_row<0>(acc1, cb, 14, ev, od);

    // Store: even-aligned 8B pairs; OW=4082 even -> pairs never straddle rows.
    const int oxg = tx0 + oxl;
#pragma unroll
    for (int ry = 0; ry < 2; ++ry) {
        int oy = ty0 + oyl + ry;
        if (oy < OHd) {
            const u64* accp = ry ? acc1 : acc0;
            float* orow = out + (size_t)oy * OWd;
#pragma unroll
            for (int p = 0; p < 4; ++p) {
                int ox = oxg + 2 * p;
                if (ox < OWd) {
                    *(u64*)(orow + ox) = accp[p];
                }
            }
        }
    }
}

extern "C" void kernel_launch(void* const* d_in, const int* in_sizes, int n_in,
                              void* d_out, int out_size) {
    const float* x    = (const float*)d_in[0];
    const float* wt   = (const float*)d_in[1];
    const float* bias = (const float*)d_in[2];
    float* out        = (float*)d_out;

    // Build (w,w) u64 pairs in __constant__ memory (async D2D, graph-capturable).
    void* cw_addr = nullptr;
    cudaGetSymbolAddress(&cw_addr, c_w2);
    cudaMemcpy2DAsync(cw_addr, 8, wt, 4, 4, KHd * KWd,
                      cudaMemcpyDeviceToDevice, 0);
    cudaMemcpy2DAsync((char*)cw_addr + 4, 8, wt, 4, 4, KHd * KWd,
                      cudaMemcpyDeviceToDevice, 0);

    dim3 grid((OWd + BXo - 1) / BXo, (OHd + BYo - 1) / BYo);  // (32, 128)
    conv2d_f32x2_kernel<<<grid, 256>>>(x, bias, out);
}

// round 16
// speedup vs baseline: 1.8302x; 1.0026x over previous
#include <cuda_runtime.h>

// Conv2D valid cross-correlation: x[4096,4096] fp32 * w[15,15] + bias -> out[4082,4082]
//
// v11: v4 base (RY=2, cmem weights, regs 38, 137us) + LDC.128 weight pair
//  loads through EXPLICIT const-space asm (cvta.to.const + ld.const.v2.u64).
//  Theory: v4's 60 scalar LDC per row-step hit the GPR-dest const-port floor
//  (8 cyc/SMSP) = 480 cyc, co-saturating with 240 FFMA2 * rt2 = 480 fma cyc.
//  Pair loads cut that to 16 loads = 128 cyc -> fma pipe sole limiter.
//  v8 tried this with a C pointer cast and ptxas dropped the const space
//  (generic loads, L2 3x); asm cannot be mis-inferred.
//  Row parity (15r odd/even vs 16B alignment) via conv_row<P>, loop unrolled x2.

#define Hd 4096
#define Wd 4096
#define KHd 15
#define KWd 15
#define OHd (Hd - KHd + 1)   // 4082
#define OWd (Wd - KWd + 1)   // 4082

#define BXo 128
#define BYo 32
#define TILE_ROWS (BYo + KHd - 1)   // 46
#define SSTR 144                     // floats per smem row

typedef unsigned long long u64;

// (w,w) pairs, rows contiguous (15 u64/row), padded so the aligned 16-u64
// window of row 14 (indices 210..225) stays in bounds.
__constant__ __align__(16) u64 c_w2[240];

__device__ __forceinline__ u64 pack2(float lo, float hi) {
    u64 r;
    asm("mov.b64 %0, {%1, %2};" : "=l"(r) : "f"(lo), "f"(hi));
    return r;
}

__device__ __forceinline__ u64 fma2(u64 a, u64 b, u64 c) {
    u64 d;
    asm("fma.rn.f32x2 %0, %1, %2, %3;" : "=l"(d) : "l"(a), "l"(b), "l"(c));
    return d;
}

// odd pair = {hi(a), lo(b)} : exactly 2 SASS MOVs
__device__ __forceinline__ u64 mkodd(u64 a, u64 b) {
    u64 r;
    asm("{\n\t"
        ".reg .b32 al, ah, bl, bh;\n\t"
        "mov.b64 {al, ah}, %1;\n\t"
        "mov.b64 {bl, bh}, %2;\n\t"
        "mov.b64 %0, {ah, bl};\n\t"
        "}" : "=l"(r) : "l"(a), "l"(b));
    return r;
}

// One ky-row of the stencil on 4 output pairs. Weight row `row` (parity P ==
// row & 1) read as 8x LDC.128 from the 16B-aligned window starting at
// element 15*row - P:
//   P=0: q[i] = (w[2i], w[2i+1])   (q[7].y unused)
//   P=1: q[i] = (w[2i-1], w[2i])   (q[0].x unused)
template<int P>
__device__ __forceinline__ void conv_row(u64 acc[4], u64 cb, int row,
                                         const u64 ev[12], const u64 od[10]) {
    u64 base = cb + (u64)(15 * row - P) * 8u;
#pragma unroll
    for (int i = 0; i < 8; ++i) {
        u64 wx, wy;
        asm("ld.const.v2.u64 {%0, %1}, [%2];"
            : "=l"(wx), "=l"(wy) : "l"(base + 16u * i));
        if (P == 0) {
#pragma unroll
            for (int p = 0; p < 4; ++p)
                acc[p] = fma2(ev[i + p], wx, acc[p]);
            if (i < 7) {
#pragma unroll
                for (int p = 0; p < 4; ++p)
                    acc[p] = fma2(od[i + p], wy, acc[p]);
            }
        } else {
#pragma unroll
            for (int p = 0; p < 4; ++p)
                acc[p] = fma2(ev[i + p], wy, acc[p]);
            if (i >= 1) {
#pragma unroll
                for (int p = 0; p < 4; ++p)
                    acc[p] = fma2(od[i - 1 + p], wx, acc[p]);
            }
        }
    }
}

// Load 12 even pairs (direct ulonglong2) and derive 10 odd pairs (2 MOVs each).
__device__ __forceinline__ void load_row(const float* __restrict__ srow,
                                         u64 ev[12], u64 od[10]) {
#pragma unroll
    for (int i = 0; i < 6; ++i) {
        ulonglong2 v = ((const ulonglong2*)srow)[i];
        ev[2 * i + 0] = v.x;
        ev[2 * i + 1] = v.y;
    }
#pragma unroll
    for (int j = 0; j < 10; ++j)
        od[j] = mkodd(ev[j], ev[j + 1]);
}

__global__ __launch_bounds__(256, 3)
void conv2d_f32x2_kernel(const float* __restrict__ x,
                         const float* __restrict__ bias,
                         float* __restrict__ out) {
    __shared__ float s_in[TILE_ROWS * SSTR];   // 46*144*4 = 26496 B

    const int tid = threadIdx.x;
    const int tx0 = blockIdx.x * BXo;
    const int ty0 = blockIdx.y * BYo;

    // Stage input tile: 46 rows x 144 floats.
    for (int s = tid; s < TILE_ROWS * 36; s += 256) {
        int rr = s / 36;
        int cc = (s - rr * 36) * 4;
        int gy = ty0 + rr;
        int gx = tx0 + cc;
        float4 v;
        if (gy < Hd && gx + 3 < Wd) {
            v = *(const float4*)(x + (size_t)gy * Wd + gx);
        } else {
            v.x = (gy < Hd && gx + 0 < Wd) ? x[(size_t)gy * Wd + gx + 0] : 0.f;
            v.y = (gy < Hd && gx + 1 < Wd) ? x[(size_t)gy * Wd + gx + 1] : 0.f;
            v.z = (gy < Hd && gx + 2 < Wd) ? x[(size_t)gy * Wd + gx + 2] : 0.f;
            v.w = (gy < Hd && gx + 3 < Wd) ? x[(size_t)gy * Wd + gx + 3] : 0.f;
        }
        *(float4*)&s_in[rr * SSTR + cc] = v;
    }
    __syncthreads();

    // Const-space base address of c_w2 (explicit: cannot lose the space).
    u64 cb;
    asm("cvta.to.const.u64 %0, %1;" : "=l"(cb) : "l"((const u64*)c_w2));

    const int tx = tid & 15;
    const int ty = tid >> 4;
    const int oxl = tx * 8;   // 8 outputs in x
    const int oyl = ty * 2;   // 2 outputs in y

    const float b = bias[0];
    const u64 b2 = pack2(b, b);
    u64 acc0[4] = {b2, b2, b2, b2};
    u64 acc1[4] = {b2, b2, b2, b2};

    u64 ev[12], od[10];
    const float* sbase = &s_in[oyl * SSTR + oxl];

    // r = 0: only output row 0 (weight row 0, parity 0)
    load_row(sbase + 0 * SSTR, ev, od);
    conv_row<0>(acc0, cb, 0, ev, od);

    // r = 1..14, x2 unrolled so weight-row parity is compile-time.
#pragma unroll 1
    for (int r = 1; r <= 13; r += 2) {
        // input row r (odd): acc0 uses weight row r (P=1), acc1 row r-1 (P=0)
        load_row(sbase + r * SSTR, ev, od);
        conv_row<1>(acc0, cb, r,     ev, od);
        conv_row<0>(acc1, cb, r - 1, ev, od);
        // input row r+1 (even): acc0 row r+1 (P=0), acc1 row r (P=1)
        load_row(sbase + (r + 1) * SSTR, ev, od);
        conv_row<0>(acc0, cb, r + 1, ev, od);
        conv_row<1>(acc1, cb, r,     ev, od);
    }

    // r = 15: only output row 1 (weight row 14, parity 0)
    load_row(sbase + 15 * SSTR, ev, od);
    conv_row<0>(acc1, cb, 14, ev, od);

    // Store: even-aligned 8B pairs; OW=4082 even -> pairs never straddle rows.
    const int oxg = tx0 + oxl;
#pragma unroll
    for (int ry = 0; ry < 2; ++ry) {
        int oy = ty0 + oyl + ry;
        if (oy < OHd) {
            const u64* accp = ry ? acc1 : acc0;
            float* orow = out + (size_t)oy * OWd;
#pragma unroll
            for (int p = 0; p < 4; ++p) {
                int ox = oxg + 2 * p;
                if (ox < OWd) {
                    *(u64*)(orow + ox) = accp[p];
                }
            }
        }
    }
}

extern "C" void kernel_launch(void* const* d_in, const int* in_sizes, int n_in,
                              void* d_out, int out_size) {
    const float* x    = (const float*)d_in[0];
    const float* wt   = (const float*)d_in[1];
    const float* bias = (const float*)d_in[2];
    float* out        = (float*)d_out;

    // Build (w,w) u64 pairs in __constant__ memory (async D2D, graph-capturable).
    void* cw_addr = nullptr;
    cudaGetSymbolAddress(&cw_addr, c_w2);
    cudaMemcpy2DAsync(cw_addr, 8, wt, 4, 4, KHd * KWd,
                      cudaMemcpyDeviceToDevice, 0);
    cudaMemcpy2DAsync((char*)cw_addr + 4, 8, wt, 4, 4, KHd * KWd,
                      cudaMemcpyDeviceToDevice, 0);

    dim3 grid((OWd + BXo - 1) / BXo, (OHd + BYo - 1) / BYo);  // (32, 128)
    conv2d_f32x2_kernel<<<grid, 256>>>(x, bias, out);
}